// round 7
// baseline (speedup 1.0000x reference)
#include <cuda_runtime.h>
#include <cuda_bf16.h>

#define ALPHA_MARGIN 1.0f

// Fully-resident persistent kernel (5 CTAs/SM x 148 SMs). 2 pairs per
// warp-iteration, double-buffered prefetch of X tiles AND labels.
// Interleaved butterflies; fused int2 label load + float2 output store.
__global__ __launch_bounds__(256) void contrastive_loss_kernel(
    const float* __restrict__ X,
    const int*   __restrict__ y,
    float*       __restrict__ out,
    int n_pairs)
{
    const int lane   = threadIdx.x & 31;
    const int gwarp  = (blockIdx.x * blockDim.x + threadIdx.x) >> 5;
    const int nwarps = (gridDim.x * blockDim.x) >> 5;
    const int stride = nwarps * 2;

    const float4* Xv = reinterpret_cast<const float4*>(X);
    int p = gwarp * 2;   // always even; n_pairs is even (524288)

    float4 a0, b0, a1, b1;
    int2 adj = make_int2(0, 0);
    if (p + 1 < n_pairs) {
        const float4* r0 = Xv + (size_t)p * 64;
        a0 = __ldg(r0 + lane);
        b0 = __ldg(r0 + 32 + lane);
        a1 = __ldg(r0 + 64 + lane);
        b1 = __ldg(r0 + 96 + lane);
        if (lane == 0) adj = *reinterpret_cast<const int2*>(y + p);
    }

    while (p + 1 < n_pairs) {
        const int pn = p + stride;

        // Prefetch next iteration (both pairs contiguous: 4 x LDG.128)
        float4 na0, nb0, na1, nb1;
        int2 nadj = make_int2(0, 0);
        if (pn + 1 < n_pairs) {
            const float4* r0 = Xv + (size_t)pn * 64;
            na0 = __ldg(r0 + lane);
            nb0 = __ldg(r0 + 32 + lane);
            na1 = __ldg(r0 + 64 + lane);
            nb1 = __ldg(r0 + 96 + lane);
            if (lane == 0) nadj = *reinterpret_cast<const int2*>(y + pn);
        }

        // Partial sums for both pairs
        float dx0 = a0.x - b0.x, dy0 = a0.y - b0.y;
        float dz0 = a0.z - b0.z, dw0 = a0.w - b0.w;
        float s0 = dx0 * dx0 + dy0 * dy0 + dz0 * dz0 + dw0 * dw0;

        float dx1 = a1.x - b1.x, dy1 = a1.y - b1.y;
        float dz1 = a1.z - b1.z, dw1 = a1.w - b1.w;
        float s1 = dx1 * dx1 + dy1 * dy1 + dz1 * dz1 + dw1 * dw1;

        // Interleaved butterflies (independent chains dual-issue)
        #pragma unroll
        for (int o = 16; o > 0; o >>= 1) {
            s0 += __shfl_xor_sync(0xffffffffu, s0, o);
            s1 += __shfl_xor_sync(0xffffffffu, s1, o);
        }

        if (lane == 0) {
            float l0 = (adj.x == 1) ? s0
                     : (adj.x == 0) ? fmaxf(ALPHA_MARGIN - s0, 0.0f)
                     : 0.0f;
            float l1 = (adj.y == 1) ? s1
                     : (adj.y == 0) ? fmaxf(ALPHA_MARGIN - s1, 0.0f)
                     : 0.0f;
            *reinterpret_cast<float2*>(out + p) = make_float2(l0, l1);
        }

        a0 = na0; b0 = nb0; a1 = na1; b1 = nb1;
        adj = nadj;
        p = pn;
    }
}

extern "C" void kernel_launch(void* const* d_in, const int* in_sizes, int n_in,
                              void* d_out, int out_size)
{
    const float* X = (const float*)d_in[0];
    const int*   y = (const int*)d_in[1];
    float*       out = (float*)d_out;

    int n_pairs = out_size;          // B*N*N = 524288 (even)
    int blocks  = 5 * 148;           // fully resident single wave
    contrastive_loss_kernel<<<blocks, 256>>>(X, y, out, n_pairs);
}

// round 8
// speedup vs baseline: 1.0031x; 1.0031x over previous
#include <cuda_runtime.h>
#include <cuda_bf16.h>

#define ALPHA_MARGIN 1.0f

// Fully-resident persistent kernel (5 CTAs/SM x 148 SMs). 2 pairs per
// warp-iteration, double-buffered prefetch of X tiles and labels (int2).
// Sequential per-pair reduce+store so pair0's epilogue overlaps pair1's
// butterfly (best-measured R5 structure).
__global__ __launch_bounds__(256) void contrastive_loss_kernel(
    const float* __restrict__ X,
    const int*   __restrict__ y,
    float*       __restrict__ out,
    int n_pairs)
{
    const int lane   = threadIdx.x & 31;
    const int gwarp  = (blockIdx.x * blockDim.x + threadIdx.x) >> 5;
    const int nwarps = (gridDim.x * blockDim.x) >> 5;
    const int stride = nwarps * 2;

    const float4* Xv = reinterpret_cast<const float4*>(X);
    int p = gwarp * 2;   // always even; n_pairs = 524288 is even

    float4 a0, b0, a1, b1;
    int2 adj = make_int2(0, 0);
    if (p + 1 < n_pairs) {
        const float4* r = Xv + (size_t)p * 64;
        a0 = __ldg(r + lane);
        b0 = __ldg(r + 32 + lane);
        a1 = __ldg(r + 64 + lane);
        b1 = __ldg(r + 96 + lane);
        if (lane == 0) adj = *reinterpret_cast<const int2*>(y + p);
    }

    while (p + 1 < n_pairs) {
        const int pn = p + stride;

        // Prefetch next iteration before reducing current
        float4 na0, nb0, na1, nb1;
        int2 nadj = make_int2(0, 0);
        if (pn + 1 < n_pairs) {
            const float4* r = Xv + (size_t)pn * 64;
            na0 = __ldg(r + lane);
            nb0 = __ldg(r + 32 + lane);
            na1 = __ldg(r + 64 + lane);
            nb1 = __ldg(r + 96 + lane);
            if (lane == 0) nadj = *reinterpret_cast<const int2*>(y + pn);
        }

        // Pair p
        {
            float dx = a0.x - b0.x, dy = a0.y - b0.y;
            float dz = a0.z - b0.z, dw = a0.w - b0.w;
            float s = dx * dx + dy * dy + dz * dz + dw * dw;
            #pragma unroll
            for (int o = 16; o > 0; o >>= 1)
                s += __shfl_xor_sync(0xffffffffu, s, o);
            if (lane == 0) {
                out[p] = (adj.x == 1) ? s
                       : (adj.x == 0) ? fmaxf(ALPHA_MARGIN - s, 0.0f)
                       : 0.0f;
            }
        }

        // Pair p+1
        {
            float dx = a1.x - b1.x, dy = a1.y - b1.y;
            float dz = a1.z - b1.z, dw = a1.w - b1.w;
            float s = dx * dx + dy * dy + dz * dz + dw * dw;
            #pragma unroll
            for (int o = 16; o > 0; o >>= 1)
                s += __shfl_xor_sync(0xffffffffu, s, o);
            if (lane == 0) {
                out[p + 1] = (adj.y == 1) ? s
                           : (adj.y == 0) ? fmaxf(ALPHA_MARGIN - s, 0.0f)
                           : 0.0f;
            }
        }

        a0 = na0; b0 = nb0; a1 = na1; b1 = nb1;
        adj = nadj;
        p = pn;
    }
}

extern "C" void kernel_launch(void* const* d_in, const int* in_sizes, int n_in,
                              void* d_out, int out_size)
{
    const float* X = (const float*)d_in[0];
    const int*   y = (const int*)d_in[1];
    float*       out = (float*)d_out;

    int n_pairs = out_size;          // B*N*N = 524288 (even)
    int blocks  = 5 * 148;           // fully resident single wave
    contrastive_loss_kernel<<<blocks, 256>>>(X, y, out, n_pairs);
}

// round 9
// speedup vs baseline: 1.0145x; 1.0114x over previous
#include <cuda_runtime.h>
#include <cuda_bf16.h>

#define ALPHA_MARGIN 1.0f

// Fully-resident persistent kernel: grid sized so every CTA is resident from
// wave 1 (5 CTAs/SM x 148 SMs). Each warp: 2 pairs per iteration, 4 coalesced
// LDG.128 per lane, next iteration prefetched before the current reduction.
// (Exact best-measured configuration — R5, 80.35us.)
__global__ __launch_bounds__(256) void contrastive_loss_kernel(
    const float* __restrict__ X,
    const int*   __restrict__ y,
    float*       __restrict__ out,
    int n_pairs)
{
    const int lane   = threadIdx.x & 31;
    const int gwarp  = (blockIdx.x * blockDim.x + threadIdx.x) >> 5;
    const int nwarps = (gridDim.x * blockDim.x) >> 5;
    const int stride = nwarps * 2;

    const float4* Xv = reinterpret_cast<const float4*>(X);
    int p = gwarp * 2;

    float4 a0, b0, a1, b1;
    if (p < n_pairs) {
        const float4* r0 = Xv + (size_t)p * 64;
        a0 = __ldg(r0 + lane);
        b0 = __ldg(r0 + 32 + lane);
    }
    if (p + 1 < n_pairs) {
        const float4* r1 = Xv + (size_t)(p + 1) * 64;
        a1 = __ldg(r1 + lane);
        b1 = __ldg(r1 + 32 + lane);
    }

    while (p < n_pairs) {
        const int pn = p + stride;

        // Prefetch next iteration before reducing current
        float4 na0, nb0, na1, nb1;
        if (pn < n_pairs) {
            const float4* r0 = Xv + (size_t)pn * 64;
            na0 = __ldg(r0 + lane);
            nb0 = __ldg(r0 + 32 + lane);
        }
        if (pn + 1 < n_pairs) {
            const float4* r1 = Xv + (size_t)(pn + 1) * 64;
            na1 = __ldg(r1 + lane);
            nb1 = __ldg(r1 + 32 + lane);
        }

        // Pair p
        {
            float dx = a0.x - b0.x, dy = a0.y - b0.y;
            float dz = a0.z - b0.z, dw = a0.w - b0.w;
            float s = dx * dx + dy * dy + dz * dz + dw * dw;
            #pragma unroll
            for (int o = 16; o > 0; o >>= 1)
                s += __shfl_xor_sync(0xffffffffu, s, o);
            if (lane == 0) {
                int adj = y[p];
                out[p] = (adj == 1) ? s
                       : (adj == 0) ? fmaxf(ALPHA_MARGIN - s, 0.0f)
                       : 0.0f;
            }
        }

        // Pair p+1
        if (p + 1 < n_pairs) {
            float dx = a1.x - b1.x, dy = a1.y - b1.y;
            float dz = a1.z - b1.z, dw = a1.w - b1.w;
            float s = dx * dx + dy * dy + dz * dz + dw * dw;
            #pragma unroll
            for (int o = 16; o > 0; o >>= 1)
                s += __shfl_xor_sync(0xffffffffu, s, o);
            if (lane == 0) {
                int adj = y[p + 1];
                out[p + 1] = (adj == 1) ? s
                           : (adj == 0) ? fmaxf(ALPHA_MARGIN - s, 0.0f)
                           : 0.0f;
            }
        }

        a0 = na0; b0 = nb0; a1 = na1; b1 = nb1;
        p = pn;
    }
}

extern "C" void kernel_launch(void* const* d_in, const int* in_sizes, int n_in,
                              void* d_out, int out_size)
{
    const float* X = (const float*)d_in[0];
    const int*   y = (const int*)d_in[1];
    float*       out = (float*)d_out;

    int n_pairs = out_size;                 // B*N*N = 524288
    int blocks  = 5 * 148;                  // fully resident: 5 CTAs/SM (46 regs/thr)
    contrastive_loss_kernel<<<blocks, 256>>>(X, y, out, n_pairs);
}

// round 10
// speedup vs baseline: 1.0254x; 1.0107x over previous
#include <cuda_runtime.h>
#include <cuda_bf16.h>

#define ALPHA_MARGIN 1.0f

// Persistent grid-stride kernel (best-measured config: R2, 80.38us, 86.7% DRAM).
// Each warp processes 2 pairs per iteration (4 x LDG.128 per lane, fully
// coalesced 512B chunks), with the next iteration's loads prefetched before
// the current reduction so ~8 LDG.128 stay in flight through the SHFL chain.
// This kernel is HBM-streaming-bound: 541MB compulsory traffic at the chip's
// ~6.8TB/s effective ceiling = ~79us floor; measured within noise of it.
__global__ __launch_bounds__(256) void contrastive_loss_kernel(
    const float* __restrict__ X,
    const int*   __restrict__ y,
    float*       __restrict__ out,
    int n_pairs)
{
    const int lane   = threadIdx.x & 31;
    const int gwarp  = (blockIdx.x * blockDim.x + threadIdx.x) >> 5;
    const int nwarps = (gridDim.x * blockDim.x) >> 5;
    const int stride = nwarps * 2;

    const float4* Xv = reinterpret_cast<const float4*>(X);
    int p = gwarp * 2;

    float4 a0, b0, a1, b1;
    if (p < n_pairs) {
        const float4* r0 = Xv + (size_t)p * 64;
        a0 = __ldg(r0 + lane);
        b0 = __ldg(r0 + 32 + lane);
    }
    if (p + 1 < n_pairs) {
        const float4* r1 = Xv + (size_t)(p + 1) * 64;
        a1 = __ldg(r1 + lane);
        b1 = __ldg(r1 + 32 + lane);
    }

    while (p < n_pairs) {
        const int pn = p + stride;

        // Prefetch next iteration before reducing current
        float4 na0, nb0, na1, nb1;
        if (pn < n_pairs) {
            const float4* r0 = Xv + (size_t)pn * 64;
            na0 = __ldg(r0 + lane);
            nb0 = __ldg(r0 + 32 + lane);
        }
        if (pn + 1 < n_pairs) {
            const float4* r1 = Xv + (size_t)(pn + 1) * 64;
            na1 = __ldg(r1 + lane);
            nb1 = __ldg(r1 + 32 + lane);
        }

        // Pair p
        {
            float dx = a0.x - b0.x, dy = a0.y - b0.y;
            float dz = a0.z - b0.z, dw = a0.w - b0.w;
            float s = dx * dx + dy * dy + dz * dz + dw * dw;
            #pragma unroll
            for (int o = 16; o > 0; o >>= 1)
                s += __shfl_xor_sync(0xffffffffu, s, o);
            if (lane == 0) {
                int adj = y[p];
                out[p] = (adj == 1) ? s
                       : (adj == 0) ? fmaxf(ALPHA_MARGIN - s, 0.0f)
                       : 0.0f;
            }
        }

        // Pair p+1
        if (p + 1 < n_pairs) {
            float dx = a1.x - b1.x, dy = a1.y - b1.y;
            float dz = a1.z - b1.z, dw = a1.w - b1.w;
            float s = dx * dx + dy * dy + dz * dz + dw * dw;
            #pragma unroll
            for (int o = 16; o > 0; o >>= 1)
                s += __shfl_xor_sync(0xffffffffu, s, o);
            if (lane == 0) {
                int adj = y[p + 1];
                out[p + 1] = (adj == 1) ? s
                           : (adj == 0) ? fmaxf(ALPHA_MARGIN - s, 0.0f)
                           : 0.0f;
            }
        }

        a0 = na0; b0 = nb0; a1 = na1; b1 = nb1;
        p = pn;
    }
}

extern "C" void kernel_launch(void* const* d_in, const int* in_sizes, int n_in,
                              void* d_out, int out_size)
{
    const float* X = (const float*)d_in[0];
    const int*   y = (const int*)d_in[1];
    float*       out = (float*)d_out;

    int n_pairs = out_size;      // B*N*N = 524288
    int blocks  = 2048;          // best-measured shape (R2: 80.38us, 86.7% DRAM)
    contrastive_loss_kernel<<<blocks, 256>>>(X, y, out, n_pairs);
}